// round 16
// baseline (speedup 1.0000x reference)
#include <cuda_runtime.h>
#include <cuda_fp16.h>

#define NN 50000
#define EE 800000
#define HCH 64
#define ECH 32
#define NHD 4
#define PH 16

typedef unsigned long long u64;
typedef unsigned int u32;

// Scratch (device globals).
__device__ __align__(16) __half g_KV [NN * 128];
__device__ __align__(16) __half g_Qth[NN * 64];
__device__ __align__(16) float  g_Qb[NN * NHD];
__device__ __align__(16) __half g_Wk[(size_t)EE * 16];
__device__ __align__(16) __half g_Wv[(size_t)EE * 16];
__device__ __align__(16) float  g_U [NN * HCH];
__device__ __align__(16) float  g_D [NN * NHD];
__device__ int g_idx64;

__device__ __forceinline__ float ssp(float v) {
    return fmaxf(v, 0.f) + __logf(fmaf(0.5f, __expf(-fabsf(v)), 0.5f));
}

// ---- packed f32x2 helpers ----
__device__ __forceinline__ u64 pack2(float lo, float hi) {
    u64 d; asm("mov.b64 %0, {%1, %2};" : "=l"(d) : "f"(lo), "f"(hi)); return d;
}
__device__ __forceinline__ void unpack2(u64 a, float& lo, float& hi) {
    asm("mov.b64 {%0, %1}, %2;" : "=f"(lo), "=f"(hi) : "l"(a));
}
__device__ __forceinline__ u64 ffma2(u64 a, u64 b, u64 c) {
    u64 d; asm("fma.rn.f32x2 %0, %1, %2, %3;" : "=l"(d) : "l"(a), "l"(b), "l"(c)); return d;
}
__device__ __forceinline__ u64 fmul2(u64 a, u64 b) {
    u64 d; asm("mul.rn.f32x2 %0, %1, %2;" : "=l"(d) : "l"(a), "l"(b)); return d;
}
__device__ __forceinline__ void cvt8(uint4 r, u64* out) {
    const __half2* h = reinterpret_cast<const __half2*>(&r);
#pragma unroll
    for (int i = 0; i < 4; i++) {
        float2 f = __half22float2(h[i]);
        out[i] = pack2(f.x, f.y);
    }
}
__device__ __forceinline__ void ld16(const float* __restrict__ p, float* r) {
#pragma unroll
    for (int i = 0; i < 4; i++) {
        float4 v = reinterpret_cast<const float4*>(p)[i];
        r[4*i+0] = v.x; r[4*i+1] = v.y; r[4*i+2] = v.z; r[4*i+3] = v.w;
    }
}
__device__ __forceinline__ uint4 toh8(const float* r) {
    uint4 o;
    __half2* h = reinterpret_cast<__half2*>(&o);
#pragma unroll
    for (int i = 0; i < 4; i++)
        h[i] = __float22half2_rn(make_float2(r[2*i], r[2*i+1]));
    return o;
}
__device__ __forceinline__ u32 h2(float a, float b) {
    __half2 h = __floats2half2_rn(a, b);
    return *reinterpret_cast<u32*>(&h);
}
__device__ __forceinline__ void red_add4(float* p, float a, float b, float c, float d) {
    asm volatile("red.global.add.v4.f32 [%0], {%1,%2,%3,%4};"
                 :: "l"(__cvta_generic_to_global(p)),
                    "f"(a), "f"(b), "f"(c), "f"(d) : "memory");
}
__device__ __forceinline__ void red_add1(float* p, float a) {
    asm volatile("red.global.add.f32 [%0], %1;"
                 :: "l"(__cvta_generic_to_global(p)), "f"(a) : "memory");
}
__device__ __forceinline__ void mma16816(float d[4], const u32 a[4], const u32 b[2]) {
    asm volatile("mma.sync.aligned.m16n8k16.row.col.f32.f16.f16.f32 "
        "{%0,%1,%2,%3},{%4,%5,%6,%7},{%8,%9},{%0,%1,%2,%3};"
        : "+f"(d[0]), "+f"(d[1]), "+f"(d[2]), "+f"(d[3])
        : "r"(a[0]), "r"(a[1]), "r"(a[2]), "r"(a[3]), "r"(b[0]), "r"(b[1]));
}

// ---------------------------------------------------------------------------
__global__ void k_detect(const int* __restrict__ ei_w) {
    int bad = __syncthreads_or(ei_w[2 * threadIdx.x + 1] != 0);
    if (threadIdx.x == 0) g_idx64 = bad ? 0 : 1;
}

// ---------------------------------------------------------------------------
// Kernel 1: node precompute (unchanged)
// ---------------------------------------------------------------------------
__global__ __launch_bounds__(256)
void k_nodes(const float* __restrict__ x,
             const float* __restrict__ kw, const float* __restrict__ qw,
             const float* __restrict__ vw,
             const float* __restrict__ wklw, const float* __restrict__ wklb) {
    __shared__ __align__(16) float s_k[1024], s_q[1024], s_v[1024], s_l[256], s_lb[16];
    for (int i = threadIdx.x; i < 1024; i += 256) {
        s_k[i] = kw[i]; s_q[i] = qw[i]; s_v[i] = vw[i];
    }
    if (threadIdx.x < 256) s_l[threadIdx.x] = wklw[threadIdx.x];
    if (threadIdx.x < 16)  s_lb[threadIdx.x] = wklb[threadIdx.x];
    __syncthreads();

    int t = blockIdx.x * 256 + threadIdx.x;
    if (t >= NN * NHD) return;
    int n = t >> 2, h = t & 3;

    float xv[PH];
    ld16(x + (size_t)n * HCH + h * PH, xv);

    const float4* wkh = (const float4*)(s_k + h * 256);
    const float4* wqh = (const float4*)(s_q + h * 256);
    const float4* wvh = (const float4*)(s_v + h * 256);

    float kk[PH], vv[PH], qq[PH];
#pragma unroll
    for (int o = 0; o < PH; o++) {
        float a = 0.f, b = 0.f, c = 0.f;
#pragma unroll
        for (int q = 0; q < 4; q++) {
            float4 wk = wkh[o * 4 + q];
            float4 wq = wqh[o * 4 + q];
            float4 wv = wvh[o * 4 + q];
            a += xv[4*q]*wk.x + xv[4*q+1]*wk.y + xv[4*q+2]*wk.z + xv[4*q+3]*wk.w;
            b += xv[4*q]*wq.x + xv[4*q+1]*wq.y + xv[4*q+2]*wq.z + xv[4*q+3]*wq.w;
            c += xv[4*q]*wv.x + xv[4*q+1]*wv.y + xv[4*q+2]*wv.z + xv[4*q+3]*wv.w;
        }
        kk[o] = a; qq[o] = b; vv[o] = c;
    }

    float qt[PH];
#pragma unroll
    for (int i = 0; i < PH; i++) {
        float a = 0.f;
#pragma unroll
        for (int o = 0; o < PH; o++) a += qq[o] * s_l[o * PH + i];
        qt[i] = a;
    }
    float qb = 0.f;
#pragma unroll
    for (int o = 0; o < PH; o++) qb += qq[o] * s_lb[o];

    uint4* kvb = reinterpret_cast<uint4*>(g_KV + (size_t)n * 128);
    kvb[h * 2 + 0] = toh8(kk);
    kvb[h * 2 + 1] = toh8(kk + 8);
    kvb[8 + h * 2 + 0] = toh8(vv);
    kvb[8 + h * 2 + 1] = toh8(vv + 8);
    uint4* qtb = reinterpret_cast<uint4*>(g_Qth + (size_t)n * 64);
    qtb[h * 2 + 0] = toh8(qt);
    qtb[h * 2 + 1] = toh8(qt + 8);
    g_Qb[t] = qb;

    float4 z = make_float4(0.f, 0.f, 0.f, 0.f);
#pragma unroll
    for (int i = 0; i < 4; i++)
        reinterpret_cast<float4*>(g_U + (size_t)t * PH)[i] = z;
    g_D[t] = 0.f;
}

// ---------------------------------------------------------------------------
// Kernel 2a (tensor-core MLP, pipelined). NEW: layer2 block-diagonal zero-tile
// skip — out-tiles 0,1 use only k-half 0 (wk2), tiles 2,3 only k-half 1 (wv2)
// -> layer2 MMAs 8 -> 4 per warp-tile (total 16 -> 12, -25%).
// ---------------------------------------------------------------------------
#define MLP_GRID 1480
__global__ __launch_bounds__(256)
void k_mlp(const float* __restrict__ ea,
           const float* __restrict__ wk1, const float* __restrict__ bk1,
           const float* __restrict__ wk2, const float* __restrict__ bk2,
           const float* __restrict__ wv1, const float* __restrict__ bv1,
           const float* __restrict__ wv2, const float* __restrict__ bv2) {
    __shared__ __align__(16) float s_w1[32 * 33];
    __shared__ __align__(16) float s_w2[32 * 33];
    __shared__ float s_b1[32], s_b2[32];
    __shared__ __align__(16) __half s_a[128 * 36];

    int tid = threadIdx.x;
    for (int idx = tid; idx < 1024; idx += 256) {
        int j = idx >> 5, i = idx & 31;
        float w1 = (j < 16) ? wk1[j * 32 + i] : wv1[(j - 16) * 32 + i];
        float w2 = 0.f;
        if (j < 16 && i < 16)   w2 = wk2[j * 16 + i];
        if (j >= 16 && i >= 16) w2 = wv2[(j - 16) * 16 + (i - 16)];
        s_w1[i * 33 + j] = w1;
        s_w2[i * 33 + j] = w2;
    }
    if (tid < 32) {
        s_b1[tid] = (tid < 16) ? bk1[tid] : bv1[tid - 16];
        s_b2[tid] = (tid < 16) ? bk2[tid] : bv2[tid - 16];
    }
    __syncthreads();

    int lane = tid & 31;
    int g = lane >> 2, t = lane & 3;
    int warp = tid >> 5;

    // B1: full; B2: only the nonzero k-half per out-tile (block diagonal)
    u32 B1[4][2][2], B2n[4][2];
    float bia1[4][2], bia2[4][2];
#pragma unroll
    for (int nt = 0; nt < 4; nt++) {
        int j = nt * 8 + g;
        int kk2 = nt >> 1;                  // nonzero k-half for layer2
#pragma unroll
        for (int kk = 0; kk < 2; kk++) {
#pragma unroll
            for (int r = 0; r < 2; r++) {
                int i0 = kk * 16 + r * 8 + t * 2;
                B1[nt][kk][r] = h2(s_w1[i0 * 33 + j], s_w1[(i0 + 1) * 33 + j]);
            }
        }
#pragma unroll
        for (int r = 0; r < 2; r++) {
            int i0 = kk2 * 16 + r * 8 + t * 2;
            B2n[nt][r] = h2(s_w2[i0 * 33 + j], s_w2[(i0 + 1) * 33 + j]);
        }
        bia1[nt][0] = s_b1[nt * 8 + t * 2]; bia1[nt][1] = s_b1[nt * 8 + t * 2 + 1];
        bia2[nt][0] = s_b2[nt * 8 + t * 2]; bia2[nt][1] = s_b2[nt * 8 + t * 2 + 1];
    }

    long long stride = (long long)gridDim.x * 128;
    long long base = (long long)blockIdx.x * 128;
    const float4* eab = reinterpret_cast<const float4*>(ea);

    float4 pre[4];
#pragma unroll
    for (int kq = 0; kq < 4; kq++) pre[kq] = eab[base * 8 + tid + kq * 256];

    for (; base < EE; base += stride) {
        __syncthreads();
#pragma unroll
        for (int kq = 0; kq < 4; kq++) {
            int f = tid + kq * 256;
            int r = f >> 3, c4 = f & 7;
            *(u32*)&s_a[r * 36 + c4 * 4 + 0] = h2(pre[kq].x, pre[kq].y);
            *(u32*)&s_a[r * 36 + c4 * 4 + 2] = h2(pre[kq].z, pre[kq].w);
        }
        __syncthreads();
        long long nb = base + stride;
        if (nb < EE) {
#pragma unroll
            for (int kq = 0; kq < 4; kq++) pre[kq] = eab[nb * 8 + tid + kq * 256];
        }

        const __half* arow0 = &s_a[(warp * 16 + g) * 36];
        const __half* arow1 = &s_a[(warp * 16 + g + 8) * 36];
        u32 A[2][4];
#pragma unroll
        for (int kk = 0; kk < 2; kk++) {
            A[kk][0] = *(const u32*)&arow0[kk * 16 + t * 2];
            A[kk][1] = *(const u32*)&arow1[kk * 16 + t * 2];
            A[kk][2] = *(const u32*)&arow0[kk * 16 + t * 2 + 8];
            A[kk][3] = *(const u32*)&arow1[kk * 16 + t * 2 + 8];
        }

        float C[4][4];
#pragma unroll
        for (int nt = 0; nt < 4; nt++) {
            C[nt][0] = C[nt][1] = C[nt][2] = C[nt][3] = 0.f;
            mma16816(C[nt], A[0], B1[nt][0]);
            mma16816(C[nt], A[1], B1[nt][1]);
        }

        u32 A2[2][4];
#pragma unroll
        for (int kk = 0; kk < 2; kk++) {
            int na = 2 * kk, nb2 = 2 * kk + 1;
            A2[kk][0] = h2(ssp(C[na][0] + bia1[na][0]), ssp(C[na][1] + bia1[na][1]));
            A2[kk][1] = h2(ssp(C[na][2] + bia1[na][0]), ssp(C[na][3] + bia1[na][1]));
            A2[kk][2] = h2(ssp(C[nb2][0] + bia1[nb2][0]), ssp(C[nb2][1] + bia1[nb2][1]));
            A2[kk][3] = h2(ssp(C[nb2][2] + bia1[nb2][0]), ssp(C[nb2][3] + bia1[nb2][1]));
        }

        // layer2: block-diagonal -> one MMA per out-tile (nonzero k-half only)
        float D[4][4];
#pragma unroll
        for (int nt = 0; nt < 4; nt++) {
            D[nt][0] = D[nt][1] = D[nt][2] = D[nt][3] = 0.f;
            mma16816(D[nt], A2[nt >> 1], B2n[nt]);
        }

        size_t eg  = (size_t)base + warp * 16 + g;
        size_t eg8 = eg + 8;
#pragma unroll
        for (int nt = 0; nt < 4; nt++) {
            int col = nt * 8 + t * 2;
            u32 lo = h2(D[nt][0] + bia2[nt][0], D[nt][1] + bia2[nt][1]);
            u32 hi = h2(D[nt][2] + bia2[nt][0], D[nt][3] + bia2[nt][1]);
            __half* d0 = (col < 16) ? (g_Wk + eg  * 16 + col) : (g_Wv + eg  * 16 + col - 16);
            __half* d8 = (col < 16) ? (g_Wk + eg8 * 16 + col) : (g_Wv + eg8 * 16 + col - 16);
            *(u32*)d0 = lo;
            *(u32*)d8 = hi;
        }
    }
}

// ---------------------------------------------------------------------------
// Kernel 2b: attention gather pass (unchanged since R10).
// ---------------------------------------------------------------------------
__global__ __launch_bounds__(256)
void k_attn(const int* __restrict__ ei) {
    int idx = blockIdx.x * 256 + threadIdx.x;
    int e = idx >> 2, h = idx & 3;

    int row, col;
    if (g_idx64) {
        const long long* p = (const long long*)ei;
        row = (int)p[e];
        col = (int)p[(size_t)EE + e];
    } else {
        row = ei[e];
        col = ei[EE + e];
    }

    const uint4* kv  = reinterpret_cast<const uint4*>(g_KV)  + (size_t)col * 16;
    const uint4* qt  = reinterpret_cast<const uint4*>(g_Qth) + (size_t)row * 8;
    const uint4* wkp = reinterpret_cast<const uint4*>(g_Wk)  + (size_t)e * 2;

    u64 wk2[8], k2[8], q2[8];
    cvt8(wkp[0], wk2); cvt8(wkp[1], wk2 + 4);
    cvt8(kv[h * 2], k2); cvt8(kv[h * 2 + 1], k2 + 4);
    cvt8(qt[h * 2], q2); cvt8(qt[h * 2 + 1], q2 + 4);

    u64 acc = 0ull;
#pragma unroll
    for (int i = 0; i < 8; i++)
        acc = ffma2(wk2[i], fmul2(k2[i], q2[i]), acc);
    float l, hh;
    unpack2(acc, l, hh);
    float eh = __expf(l + hh + g_Qb[row * NHD + h]);

    red_add1(&g_D[row * NHD + h], eh);

    const uint4* wvp = reinterpret_cast<const uint4*>(g_Wv) + (size_t)e * 2;
    u64 wv2[8], v2[8];
    cvt8(wvp[0], wv2); cvt8(wvp[1], wv2 + 4);
    cvt8(kv[8 + h * 2], v2); cvt8(kv[8 + h * 2 + 1], v2 + 4);

    u64 eh2 = pack2(eh, eh);
    float* Up = g_U + (size_t)row * HCH + h * PH;
#pragma unroll
    for (int q = 0; q < 4; q++) {
        u64 p0 = fmul2(fmul2(wv2[2*q],   v2[2*q]),   eh2);
        u64 p1 = fmul2(fmul2(wv2[2*q+1], v2[2*q+1]), eh2);
        float a, b, c, d;
        unpack2(p0, a, b); unpack2(p1, c, d);
        red_add4(Up + 4 * q, a, b, c, d);
    }
}

// ---------------------------------------------------------------------------
// Kernel 3 (tensor-core epilogue with block-diagonal zero-tile skip)
// ---------------------------------------------------------------------------
__global__ __launch_bounds__(256)
void k_out(const float* __restrict__ x,
           const float* __restrict__ wvlw, const float* __restrict__ wvlb,
           const float* __restrict__ cenw, const float* __restrict__ cenb,
           const float* __restrict__ outw, const float* __restrict__ outb,
           float* __restrict__ y) {
    __shared__ __align__(16) __half s_in[64 * 136];
    __shared__ __align__(16) u32 s_w1[64 * 65];
    __shared__ __align__(16) u32 s_w2[64 * 33];
    __shared__ float s_finv[256];
    __shared__ int   s_flag[256];
    __shared__ float s_cb[64], s_ob[64], s_vb[16];

    int tid = threadIdx.x;
    int n0 = blockIdx.x * 64;
    u32* in32 = reinterpret_cast<u32*>(s_in);

    {
        int r = tid >> 2, hh = tid & 3;
        int n = n0 + r;
        float d = (n < NN) ? g_D[n * NHD + hh] : 0.f;
        s_finv[tid] = (d > 0.f) ? (1.f / d) : 0.f;
        s_flag[tid] = (d > 0.f) ? 1 : 0;
    }
#pragma unroll
    for (int kq = 0; kq < 4; kq++) {
        int f = tid + kq * 256;
        int r = f >> 4, c = f & 15;
        int n = n0 + r;
        float4 v = (n < NN) ? reinterpret_cast<const float4*>(x)[(size_t)n * 16 + c]
                            : make_float4(0.f, 0.f, 0.f, 0.f);
        in32[r * 68 + c * 2 + 0] = h2(v.x, v.y);
        in32[r * 68 + c * 2 + 1] = h2(v.z, v.w);
    }
    for (int idx = tid; idx < 64 * 64; idx += 256) {
        int o = idx >> 6, k2 = idx & 63;
        int i0 = 2 * k2, i1 = i0 + 1;
        float a, b;
        if (i0 < 64) {
            a = cenw[o * 64 + i0];
            b = cenw[o * 64 + i1];
        } else {
            int ip0 = i0 - 64, ip1 = i1 - 64;
            int oh = o >> 4;
            a = ((ip0 >> 4) == oh) ? wvlw[(o & 15) * 16 + (ip0 & 15)] : 0.f;
            b = ((ip1 >> 4) == oh) ? wvlw[(o & 15) * 16 + (ip1 & 15)] : 0.f;
        }
        s_w1[o * 65 + k2] = h2(a, b);
    }
    for (int idx = tid; idx < 64 * 32; idx += 256) {
        int o = idx >> 5, k2 = idx & 31;
        s_w2[o * 33 + k2] = h2(outw[o * 64 + 2 * k2], outw[o * 64 + 2 * k2 + 1]);
    }
    if (tid < 64) { s_cb[tid] = cenb[tid]; s_ob[tid] = outb[tid]; }
    if (tid < 16) s_vb[tid] = wvlb[tid];
    __syncthreads();

#pragma unroll
    for (int kq = 0; kq < 4; kq++) {
        int f = tid + kq * 256;
        int r = f >> 4, c = f & 15;
        int n = n0 + r;
        float4 v = (n < NN) ? reinterpret_cast<const float4*>(g_U)[(size_t)n * 16 + c]
                            : make_float4(0.f, 0.f, 0.f, 0.f);
        float inv = s_finv[r * 4 + (c >> 2)];
        in32[r * 68 + 32 + c * 2 + 0] = h2(v.x * inv, v.y * inv);
        in32[r * 68 + 32 + c * 2 + 1] = h2(v.z * inv, v.w * inv);
    }
    __syncthreads();

    int lane = tid & 31;
    int g = lane >> 2, t = lane & 3;
    int warp = tid >> 5;
    int mt = warp & 3;
    int nh = warp >> 2;
    int r0 = mt * 16 + g, r1 = r0 + 8;

    float C[4][4];
#pragma unroll
    for (int nt = 0; nt < 4; nt++)
        C[nt][0] = C[nt][1] = C[nt][2] = C[nt][3] = 0.f;
#pragma unroll
    for (int kk = 0; kk < 4; kk++) {
        u32 A[4];
        A[0] = in32[r0 * 68 + kk * 8 + t];
        A[1] = in32[r1 * 68 + kk * 8 + t];
        A[2] = in32[r0 * 68 + kk * 8 + 4 + t];
        A[3] = in32[r1 * 68 + kk * 8 + 4 + t];
#pragma unroll
        for (int nt = 0; nt < 4; nt++) {
            int j = (nh * 4 + nt) * 8 + g;
            u32 B[2];
            B[0] = s_w1[j * 65 + kk * 8 + t];
            B[1] = s_w1[j * 65 + kk * 8 + 4 + t];
            mma16816(C[nt], A, B);
        }
    }
#pragma unroll
    for (int hp = 0; hp < 2; hp++) {
        int kk = 4 + nh * 2 + hp;
        u32 A[4];
        A[0] = in32[r0 * 68 + kk * 8 + t];
        A[1] = in32[r1 * 68 + kk * 8 + t];
        A[2] = in32[r0 * 68 + kk * 8 + 4 + t];
        A[3] = in32[r1 * 68 + kk * 8 + 4 + t];
#pragma unroll
        for (int jj = 0; jj < 2; jj++) {
            int nt = hp * 2 + jj;
            int j = (nh * 4 + nt) * 8 + g;
            u32 B[2];
            B[0] = s_w1[j * 65 + kk * 8 + t];
            B[1] = s_w1[j * 65 + kk * 8 + 4 + t];
            mma16816(C[nt], A, B);
        }
    }

    __syncthreads();
#pragma unroll
    for (int nt = 0; nt < 4; nt++) {
        int col0 = (nh * 4 + nt) * 8 + 2 * t;
        int head = col0 >> 4;
        float vb0 = s_vb[col0 & 15], vb1 = s_vb[(col0 + 1) & 15];
        float cb0 = s_cb[col0], cb1 = s_cb[col0 + 1];
        int f0 = s_flag[r0 * 4 + head], f1 = s_flag[r1 * 4 + head];
        float t00 = ssp(C[nt][0] + cb0 + (f0 ? vb0 : 0.f));
        float t01 = ssp(C[nt][1] + cb1 + (f0 ? vb1 : 0.f));
        float t10 = ssp(C[nt][2] + cb0 + (f1 ? vb0 : 0.f));
        float t11 = ssp(C[nt][3] + cb1 + (f1 ? vb1 : 0.f));
        in32[r0 * 68 + col0 / 2] = h2(t00, t01);
        in32[r1 * 68 + col0 / 2] = h2(t10, t11);
    }
    __syncthreads();

    float D[4][4];
#pragma unroll
    for (int nt = 0; nt < 4; nt++)
        D[nt][0] = D[nt][1] = D[nt][2] = D[nt][3] = 0.f;
#pragma unroll
    for (int kk = 0; kk < 4; kk++) {
        u32 A[4];
        A[0] = in32[r0 * 68 + kk * 8 + t];
        A[1] = in32[r1 * 68 + kk * 8 + t];
        A[2] = in32[r0 * 68 + kk * 8 + 4 + t];
        A[3] = in32[r1 * 68 + kk * 8 + 4 + t];
#pragma unroll
        for (int nt = 0; nt < 4; nt++) {
            int j = (nh * 4 + nt) * 8 + g;
            u32 B[2];
            B[0] = s_w2[j * 33 + kk * 8 + t];
            B[1] = s_w2[j * 33 + kk * 8 + 4 + t];
            mma16816(D[nt], A, B);
        }
    }

    int nn0 = n0 + r0, nn1 = n0 + r1;
#pragma unroll
    for (int nt = 0; nt < 4; nt++) {
        int col = (nh * 4 + nt) * 8 + 2 * t;
        float ob0 = s_ob[col], ob1 = s_ob[col + 1];
        if (nn0 < NN)
            *reinterpret_cast<float2*>(y + (size_t)nn0 * HCH + col) =
                make_float2(D[nt][0] + ob0, D[nt][1] + ob1);
        if (nn1 < NN)
            *reinterpret_cast<float2*>(y + (size_t)nn1 * HCH + col) =
                make_float2(D[nt][2] + ob0, D[nt][3] + ob1);
    }
}

// ---------------------------------------------------------------------------
extern "C" void kernel_launch(void* const* d_in, const int* in_sizes, int n_in,
                              void* d_out, int out_size) {
    const float* x    = (const float*)d_in[0];
    const int*   ei   = (const int*)d_in[1];
    const float* ea   = (const float*)d_in[2];
    const float* kw   = (const float*)d_in[3];
    const float* qw   = (const float*)d_in[4];
    const float* vw   = (const float*)d_in[5];
    const float* wk1  = (const float*)d_in[6];
    const float* bk1  = (const float*)d_in[7];
    const float* wk2  = (const float*)d_in[8];
    const float* bk2  = (const float*)d_in[9];
    const float* wklw = (const float*)d_in[10];
    const float* wklb = (const float*)d_in[11];
    const float* wv1  = (const float*)d_in[12];
    const float* bv1  = (const float*)d_in[13];
    const float* wv2  = (const float*)d_in[14];
    const float* bv2  = (const float*)d_in[15];
    const float* wvlw = (const float*)d_in[16];
    const float* wvlb = (const float*)d_in[17];
    const float* cenw = (const float*)d_in[18];
    const float* cenb = (const float*)d_in[19];
    const float* outw = (const float*)d_in[20];
    const float* outb = (const float*)d_in[21];
    float* out = (float*)d_out;

    // k_detect launched twice (idempotent): shifts ncu's captured launch (the
    // 4th) onto k_mlp for direct profiling evidence next round.
    k_detect<<<1, 256>>>(ei);
    k_detect<<<1, 256>>>(ei);
    k_nodes<<<(NN * NHD + 255) / 256, 256>>>(x, kw, qw, vw, wklw, wklb);
    k_mlp<<<MLP_GRID, 256>>>(ea, wk1, bk1, wk2, bk2, wv1, bv1, wv2, bv2);
    k_attn<<<(EE * NHD) / 256, 256>>>(ei);
    k_out<<<(NN + 63) / 64, 256>>>(x, wvlw, wvlb, cenw, cenb,
                                   outw, outb, out);
}

// round 17
// speedup vs baseline: 1.0263x; 1.0263x over previous
#include <cuda_runtime.h>
#include <cuda_fp16.h>

#define NN 50000
#define EE 800000
#define HCH 64
#define ECH 32
#define NHD 4
#define PH 16

typedef unsigned long long u64;
typedef unsigned int u32;

// Scratch (device globals).
__device__ __align__(16) __half g_KV [NN * 128];
__device__ __align__(16) __half g_Qth[NN * 64];
__device__ __align__(16) float  g_Qb[NN * NHD];
__device__ __align__(16) __half g_Wk[(size_t)EE * 16];
__device__ __align__(16) __half g_Wv[(size_t)EE * 16];
__device__ __align__(16) float  g_U [NN * HCH];
__device__ __align__(16) float  g_D [NN * NHD];
__device__ int g_idx64;

__device__ __forceinline__ float ssp(float v) {
    return fmaxf(v, 0.f) + __logf(fmaf(0.5f, __expf(-fabsf(v)), 0.5f));
}

// ---- packed f32x2 helpers ----
__device__ __forceinline__ u64 pack2(float lo, float hi) {
    u64 d; asm("mov.b64 %0, {%1, %2};" : "=l"(d) : "f"(lo), "f"(hi)); return d;
}
__device__ __forceinline__ void unpack2(u64 a, float& lo, float& hi) {
    asm("mov.b64 {%0, %1}, %2;" : "=f"(lo), "=f"(hi) : "l"(a));
}
__device__ __forceinline__ u64 ffma2(u64 a, u64 b, u64 c) {
    u64 d; asm("fma.rn.f32x2 %0, %1, %2, %3;" : "=l"(d) : "l"(a), "l"(b), "l"(c)); return d;
}
__device__ __forceinline__ u64 fmul2(u64 a, u64 b) {
    u64 d; asm("mul.rn.f32x2 %0, %1, %2;" : "=l"(d) : "l"(a), "l"(b)); return d;
}
__device__ __forceinline__ void cvt8(uint4 r, u64* out) {
    const __half2* h = reinterpret_cast<const __half2*>(&r);
#pragma unroll
    for (int i = 0; i < 4; i++) {
        float2 f = __half22float2(h[i]);
        out[i] = pack2(f.x, f.y);
    }
}
__device__ __forceinline__ void ld16(const float* __restrict__ p, float* r) {
#pragma unroll
    for (int i = 0; i < 4; i++) {
        float4 v = reinterpret_cast<const float4*>(p)[i];
        r[4*i+0] = v.x; r[4*i+1] = v.y; r[4*i+2] = v.z; r[4*i+3] = v.w;
    }
}
__device__ __forceinline__ uint4 toh8(const float* r) {
    uint4 o;
    __half2* h = reinterpret_cast<__half2*>(&o);
#pragma unroll
    for (int i = 0; i < 4; i++)
        h[i] = __float22half2_rn(make_float2(r[2*i], r[2*i+1]));
    return o;
}
__device__ __forceinline__ u32 h2(float a, float b) {
    __half2 h = __floats2half2_rn(a, b);
    return *reinterpret_cast<u32*>(&h);
}
__device__ __forceinline__ void red_add4(float* p, float a, float b, float c, float d) {
    asm volatile("red.global.add.v4.f32 [%0], {%1,%2,%3,%4};"
                 :: "l"(__cvta_generic_to_global(p)),
                    "f"(a), "f"(b), "f"(c), "f"(d) : "memory");
}
__device__ __forceinline__ void red_add1(float* p, float a) {
    asm volatile("red.global.add.f32 [%0], %1;"
                 :: "l"(__cvta_generic_to_global(p)), "f"(a) : "memory");
}
__device__ __forceinline__ void mma16816(float d[4], const u32 a[4], const u32 b[2]) {
    asm volatile("mma.sync.aligned.m16n8k16.row.col.f32.f16.f16.f32 "
        "{%0,%1,%2,%3},{%4,%5,%6,%7},{%8,%9},{%0,%1,%2,%3};"
        : "+f"(d[0]), "+f"(d[1]), "+f"(d[2]), "+f"(d[3])
        : "r"(a[0]), "r"(a[1]), "r"(a[2]), "r"(a[3]), "r"(b[0]), "r"(b[1]));
}

// ---------------------------------------------------------------------------
// Kernel 1: node precompute. Block 0 ALSO performs the edge_index width
// detection (256-sample high-word ballot) before its normal work — this
// removes the separate k_detect launches. k_attn (launched later) reads
// g_idx64 ordered by stream dependency.
// ---------------------------------------------------------------------------
__global__ __launch_bounds__(256)
void k_nodes(const float* __restrict__ x,
             const float* __restrict__ kw, const float* __restrict__ qw,
             const float* __restrict__ vw,
             const float* __restrict__ wklw, const float* __restrict__ wklb,
             const int* __restrict__ ei_w) {
    if (blockIdx.x == 0) {
        int bad = __syncthreads_or(ei_w[2 * threadIdx.x + 1] != 0);
        if (threadIdx.x == 0) g_idx64 = bad ? 0 : 1;
    }

    __shared__ __align__(16) float s_k[1024], s_q[1024], s_v[1024], s_l[256], s_lb[16];
    for (int i = threadIdx.x; i < 1024; i += 256) {
        s_k[i] = kw[i]; s_q[i] = qw[i]; s_v[i] = vw[i];
    }
    if (threadIdx.x < 256) s_l[threadIdx.x] = wklw[threadIdx.x];
    if (threadIdx.x < 16)  s_lb[threadIdx.x] = wklb[threadIdx.x];
    __syncthreads();

    int t = blockIdx.x * 256 + threadIdx.x;
    if (t >= NN * NHD) return;
    int n = t >> 2, h = t & 3;

    float xv[PH];
    ld16(x + (size_t)n * HCH + h * PH, xv);

    const float4* wkh = (const float4*)(s_k + h * 256);
    const float4* wqh = (const float4*)(s_q + h * 256);
    const float4* wvh = (const float4*)(s_v + h * 256);

    float kk[PH], vv[PH], qq[PH];
#pragma unroll
    for (int o = 0; o < PH; o++) {
        float a = 0.f, b = 0.f, c = 0.f;
#pragma unroll
        for (int q = 0; q < 4; q++) {
            float4 wk = wkh[o * 4 + q];
            float4 wq = wqh[o * 4 + q];
            float4 wv = wvh[o * 4 + q];
            a += xv[4*q]*wk.x + xv[4*q+1]*wk.y + xv[4*q+2]*wk.z + xv[4*q+3]*wk.w;
            b += xv[4*q]*wq.x + xv[4*q+1]*wq.y + xv[4*q+2]*wq.z + xv[4*q+3]*wq.w;
            c += xv[4*q]*wv.x + xv[4*q+1]*wv.y + xv[4*q+2]*wv.z + xv[4*q+3]*wv.w;
        }
        kk[o] = a; qq[o] = b; vv[o] = c;
    }

    float qt[PH];
#pragma unroll
    for (int i = 0; i < PH; i++) {
        float a = 0.f;
#pragma unroll
        for (int o = 0; o < PH; o++) a += qq[o] * s_l[o * PH + i];
        qt[i] = a;
    }
    float qb = 0.f;
#pragma unroll
    for (int o = 0; o < PH; o++) qb += qq[o] * s_lb[o];

    uint4* kvb = reinterpret_cast<uint4*>(g_KV + (size_t)n * 128);
    kvb[h * 2 + 0] = toh8(kk);
    kvb[h * 2 + 1] = toh8(kk + 8);
    kvb[8 + h * 2 + 0] = toh8(vv);
    kvb[8 + h * 2 + 1] = toh8(vv + 8);
    uint4* qtb = reinterpret_cast<uint4*>(g_Qth + (size_t)n * 64);
    qtb[h * 2 + 0] = toh8(qt);
    qtb[h * 2 + 1] = toh8(qt + 8);
    g_Qb[t] = qb;

    float4 z = make_float4(0.f, 0.f, 0.f, 0.f);
#pragma unroll
    for (int i = 0; i < 4; i++)
        reinterpret_cast<float4*>(g_U + (size_t)t * PH)[i] = z;
    g_D[t] = 0.f;
}

// ---------------------------------------------------------------------------
// Kernel 2a (tensor-core MLP, pipelined, layer2 block-diagonal skip)
// ---------------------------------------------------------------------------
#define MLP_GRID 1480
__global__ __launch_bounds__(256)
void k_mlp(const float* __restrict__ ea,
           const float* __restrict__ wk1, const float* __restrict__ bk1,
           const float* __restrict__ wk2, const float* __restrict__ bk2,
           const float* __restrict__ wv1, const float* __restrict__ bv1,
           const float* __restrict__ wv2, const float* __restrict__ bv2) {
    __shared__ __align__(16) float s_w1[32 * 33];
    __shared__ __align__(16) float s_w2[32 * 33];
    __shared__ float s_b1[32], s_b2[32];
    __shared__ __align__(16) __half s_a[128 * 36];

    int tid = threadIdx.x;
    for (int idx = tid; idx < 1024; idx += 256) {
        int j = idx >> 5, i = idx & 31;
        float w1 = (j < 16) ? wk1[j * 32 + i] : wv1[(j - 16) * 32 + i];
        float w2 = 0.f;
        if (j < 16 && i < 16)   w2 = wk2[j * 16 + i];
        if (j >= 16 && i >= 16) w2 = wv2[(j - 16) * 16 + (i - 16)];
        s_w1[i * 33 + j] = w1;
        s_w2[i * 33 + j] = w2;
    }
    if (tid < 32) {
        s_b1[tid] = (tid < 16) ? bk1[tid] : bv1[tid - 16];
        s_b2[tid] = (tid < 16) ? bk2[tid] : bv2[tid - 16];
    }
    __syncthreads();

    int lane = tid & 31;
    int g = lane >> 2, t = lane & 3;
    int warp = tid >> 5;

    u32 B1[4][2][2], B2n[4][2];
    float bia1[4][2], bia2[4][2];
#pragma unroll
    for (int nt = 0; nt < 4; nt++) {
        int j = nt * 8 + g;
        int kk2 = nt >> 1;
#pragma unroll
        for (int kk = 0; kk < 2; kk++) {
#pragma unroll
            for (int r = 0; r < 2; r++) {
                int i0 = kk * 16 + r * 8 + t * 2;
                B1[nt][kk][r] = h2(s_w1[i0 * 33 + j], s_w1[(i0 + 1) * 33 + j]);
            }
        }
#pragma unroll
        for (int r = 0; r < 2; r++) {
            int i0 = kk2 * 16 + r * 8 + t * 2;
            B2n[nt][r] = h2(s_w2[i0 * 33 + j], s_w2[(i0 + 1) * 33 + j]);
        }
        bia1[nt][0] = s_b1[nt * 8 + t * 2]; bia1[nt][1] = s_b1[nt * 8 + t * 2 + 1];
        bia2[nt][0] = s_b2[nt * 8 + t * 2]; bia2[nt][1] = s_b2[nt * 8 + t * 2 + 1];
    }

    long long stride = (long long)gridDim.x * 128;
    long long base = (long long)blockIdx.x * 128;
    const float4* eab = reinterpret_cast<const float4*>(ea);

    float4 pre[4];
#pragma unroll
    for (int kq = 0; kq < 4; kq++) pre[kq] = eab[base * 8 + tid + kq * 256];

    for (; base < EE; base += stride) {
        __syncthreads();
#pragma unroll
        for (int kq = 0; kq < 4; kq++) {
            int f = tid + kq * 256;
            int r = f >> 3, c4 = f & 7;
            *(u32*)&s_a[r * 36 + c4 * 4 + 0] = h2(pre[kq].x, pre[kq].y);
            *(u32*)&s_a[r * 36 + c4 * 4 + 2] = h2(pre[kq].z, pre[kq].w);
        }
        __syncthreads();
        long long nb = base + stride;
        if (nb < EE) {
#pragma unroll
            for (int kq = 0; kq < 4; kq++) pre[kq] = eab[nb * 8 + tid + kq * 256];
        }

        const __half* arow0 = &s_a[(warp * 16 + g) * 36];
        const __half* arow1 = &s_a[(warp * 16 + g + 8) * 36];
        u32 A[2][4];
#pragma unroll
        for (int kk = 0; kk < 2; kk++) {
            A[kk][0] = *(const u32*)&arow0[kk * 16 + t * 2];
            A[kk][1] = *(const u32*)&arow1[kk * 16 + t * 2];
            A[kk][2] = *(const u32*)&arow0[kk * 16 + t * 2 + 8];
            A[kk][3] = *(const u32*)&arow1[kk * 16 + t * 2 + 8];
        }

        float C[4][4];
#pragma unroll
        for (int nt = 0; nt < 4; nt++) {
            C[nt][0] = C[nt][1] = C[nt][2] = C[nt][3] = 0.f;
            mma16816(C[nt], A[0], B1[nt][0]);
            mma16816(C[nt], A[1], B1[nt][1]);
        }

        u32 A2[2][4];
#pragma unroll
        for (int kk = 0; kk < 2; kk++) {
            int na = 2 * kk, nb2 = 2 * kk + 1;
            A2[kk][0] = h2(ssp(C[na][0] + bia1[na][0]), ssp(C[na][1] + bia1[na][1]));
            A2[kk][1] = h2(ssp(C[na][2] + bia1[na][0]), ssp(C[na][3] + bia1[na][1]));
            A2[kk][2] = h2(ssp(C[nb2][0] + bia1[nb2][0]), ssp(C[nb2][1] + bia1[nb2][1]));
            A2[kk][3] = h2(ssp(C[nb2][2] + bia1[nb2][0]), ssp(C[nb2][3] + bia1[nb2][1]));
        }

        float D[4][4];
#pragma unroll
        for (int nt = 0; nt < 4; nt++) {
            D[nt][0] = D[nt][1] = D[nt][2] = D[nt][3] = 0.f;
            mma16816(D[nt], A2[nt >> 1], B2n[nt]);
        }

        size_t eg  = (size_t)base + warp * 16 + g;
        size_t eg8 = eg + 8;
#pragma unroll
        for (int nt = 0; nt < 4; nt++) {
            int col = nt * 8 + t * 2;
            u32 lo = h2(D[nt][0] + bia2[nt][0], D[nt][1] + bia2[nt][1]);
            u32 hi = h2(D[nt][2] + bia2[nt][0], D[nt][3] + bia2[nt][1]);
            __half* d0 = (col < 16) ? (g_Wk + eg  * 16 + col) : (g_Wv + eg  * 16 + col - 16);
            __half* d8 = (col < 16) ? (g_Wk + eg8 * 16 + col) : (g_Wv + eg8 * 16 + col - 16);
            *(u32*)d0 = lo;
            *(u32*)d8 = hi;
        }
    }
}

// ---------------------------------------------------------------------------
// Kernel 2b: attention gather pass (unchanged since R10).
// ---------------------------------------------------------------------------
__global__ __launch_bounds__(256)
void k_attn(const int* __restrict__ ei) {
    int idx = blockIdx.x * 256 + threadIdx.x;
    int e = idx >> 2, h = idx & 3;

    int row, col;
    if (g_idx64) {
        const long long* p = (const long long*)ei;
        row = (int)p[e];
        col = (int)p[(size_t)EE + e];
    } else {
        row = ei[e];
        col = ei[EE + e];
    }

    const uint4* kv  = reinterpret_cast<const uint4*>(g_KV)  + (size_t)col * 16;
    const uint4* qt  = reinterpret_cast<const uint4*>(g_Qth) + (size_t)row * 8;
    const uint4* wkp = reinterpret_cast<const uint4*>(g_Wk)  + (size_t)e * 2;

    u64 wk2[8], k2[8], q2[8];
    cvt8(wkp[0], wk2); cvt8(wkp[1], wk2 + 4);
    cvt8(kv[h * 2], k2); cvt8(kv[h * 2 + 1], k2 + 4);
    cvt8(qt[h * 2], q2); cvt8(qt[h * 2 + 1], q2 + 4);

    u64 acc = 0ull;
#pragma unroll
    for (int i = 0; i < 8; i++)
        acc = ffma2(wk2[i], fmul2(k2[i], q2[i]), acc);
    float l, hh;
    unpack2(acc, l, hh);
    float eh = __expf(l + hh + g_Qb[row * NHD + h]);

    red_add1(&g_D[row * NHD + h], eh);

    const uint4* wvp = reinterpret_cast<const uint4*>(g_Wv) + (size_t)e * 2;
    u64 wv2[8], v2[8];
    cvt8(wvp[0], wv2); cvt8(wvp[1], wv2 + 4);
    cvt8(kv[8 + h * 2], v2); cvt8(kv[8 + h * 2 + 1], v2 + 4);

    u64 eh2 = pack2(eh, eh);
    float* Up = g_U + (size_t)row * HCH + h * PH;
#pragma unroll
    for (int q = 0; q < 4; q++) {
        u64 p0 = fmul2(fmul2(wv2[2*q],   v2[2*q]),   eh2);
        u64 p1 = fmul2(fmul2(wv2[2*q+1], v2[2*q+1]), eh2);
        float a, b, c, d;
        unpack2(p0, a, b); unpack2(p1, c, d);
        red_add4(Up + 4 * q, a, b, c, d);
    }
}

// ---------------------------------------------------------------------------
// Kernel 3 (tensor-core epilogue with block-diagonal zero-tile skip)
// ---------------------------------------------------------------------------
__global__ __launch_bounds__(256)
void k_out(const float* __restrict__ x,
           const float* __restrict__ wvlw, const float* __restrict__ wvlb,
           const float* __restrict__ cenw, const float* __restrict__ cenb,
           const float* __restrict__ outw, const float* __restrict__ outb,
           float* __restrict__ y) {
    __shared__ __align__(16) __half s_in[64 * 136];
    __shared__ __align__(16) u32 s_w1[64 * 65];
    __shared__ __align__(16) u32 s_w2[64 * 33];
    __shared__ float s_finv[256];
    __shared__ int   s_flag[256];
    __shared__ float s_cb[64], s_ob[64], s_vb[16];

    int tid = threadIdx.x;
    int n0 = blockIdx.x * 64;
    u32* in32 = reinterpret_cast<u32*>(s_in);

    {
        int r = tid >> 2, hh = tid & 3;
        int n = n0 + r;
        float d = (n < NN) ? g_D[n * NHD + hh] : 0.f;
        s_finv[tid] = (d > 0.f) ? (1.f / d) : 0.f;
        s_flag[tid] = (d > 0.f) ? 1 : 0;
    }
#pragma unroll
    for (int kq = 0; kq < 4; kq++) {
        int f = tid + kq * 256;
        int r = f >> 4, c = f & 15;
        int n = n0 + r;
        float4 v = (n < NN) ? reinterpret_cast<const float4*>(x)[(size_t)n * 16 + c]
                            : make_float4(0.f, 0.f, 0.f, 0.f);
        in32[r * 68 + c * 2 + 0] = h2(v.x, v.y);
        in32[r * 68 + c * 2 + 1] = h2(v.z, v.w);
    }
    for (int idx = tid; idx < 64 * 64; idx += 256) {
        int o = idx >> 6, k2 = idx & 63;
        int i0 = 2 * k2, i1 = i0 + 1;
        float a, b;
        if (i0 < 64) {
            a = cenw[o * 64 + i0];
            b = cenw[o * 64 + i1];
        } else {
            int ip0 = i0 - 64, ip1 = i1 - 64;
            int oh = o >> 4;
            a = ((ip0 >> 4) == oh) ? wvlw[(o & 15) * 16 + (ip0 & 15)] : 0.f;
            b = ((ip1 >> 4) == oh) ? wvlw[(o & 15) * 16 + (ip1 & 15)] : 0.f;
        }
        s_w1[o * 65 + k2] = h2(a, b);
    }
    for (int idx = tid; idx < 64 * 32; idx += 256) {
        int o = idx >> 5, k2 = idx & 31;
        s_w2[o * 33 + k2] = h2(outw[o * 64 + 2 * k2], outw[o * 64 + 2 * k2 + 1]);
    }
    if (tid < 64) { s_cb[tid] = cenb[tid]; s_ob[tid] = outb[tid]; }
    if (tid < 16) s_vb[tid] = wvlb[tid];
    __syncthreads();

#pragma unroll
    for (int kq = 0; kq < 4; kq++) {
        int f = tid + kq * 256;
        int r = f >> 4, c = f & 15;
        int n = n0 + r;
        float4 v = (n < NN) ? reinterpret_cast<const float4*>(g_U)[(size_t)n * 16 + c]
                            : make_float4(0.f, 0.f, 0.f, 0.f);
        float inv = s_finv[r * 4 + (c >> 2)];
        in32[r * 68 + 32 + c * 2 + 0] = h2(v.x * inv, v.y * inv);
        in32[r * 68 + 32 + c * 2 + 1] = h2(v.z * inv, v.w * inv);
    }
    __syncthreads();

    int lane = tid & 31;
    int g = lane >> 2, t = lane & 3;
    int warp = tid >> 5;
    int mt = warp & 3;
    int nh = warp >> 2;
    int r0 = mt * 16 + g, r1 = r0 + 8;

    float C[4][4];
#pragma unroll
    for (int nt = 0; nt < 4; nt++)
        C[nt][0] = C[nt][1] = C[nt][2] = C[nt][3] = 0.f;
#pragma unroll
    for (int kk = 0; kk < 4; kk++) {
        u32 A[4];
        A[0] = in32[r0 * 68 + kk * 8 + t];
        A[1] = in32[r1 * 68 + kk * 8 + t];
        A[2] = in32[r0 * 68 + kk * 8 + 4 + t];
        A[3] = in32[r1 * 68 + kk * 8 + 4 + t];
#pragma unroll
        for (int nt = 0; nt < 4; nt++) {
            int j = (nh * 4 + nt) * 8 + g;
            u32 B[2];
            B[0] = s_w1[j * 65 + kk * 8 + t];
            B[1] = s_w1[j * 65 + kk * 8 + 4 + t];
            mma16816(C[nt], A, B);
        }
    }
#pragma unroll
    for (int hp = 0; hp < 2; hp++) {
        int kk = 4 + nh * 2 + hp;
        u32 A[4];
        A[0] = in32[r0 * 68 + kk * 8 + t];
        A[1] = in32[r1 * 68 + kk * 8 + t];
        A[2] = in32[r0 * 68 + kk * 8 + 4 + t];
        A[3] = in32[r1 * 68 + kk * 8 + 4 + t];
#pragma unroll
        for (int jj = 0; jj < 2; jj++) {
            int nt = hp * 2 + jj;
            int j = (nh * 4 + nt) * 8 + g;
            u32 B[2];
            B[0] = s_w1[j * 65 + kk * 8 + t];
            B[1] = s_w1[j * 65 + kk * 8 + 4 + t];
            mma16816(C[nt], A, B);
        }
    }

    __syncthreads();
#pragma unroll
    for (int nt = 0; nt < 4; nt++) {
        int col0 = (nh * 4 + nt) * 8 + 2 * t;
        int head = col0 >> 4;
        float vb0 = s_vb[col0 & 15], vb1 = s_vb[(col0 + 1) & 15];
        float cb0 = s_cb[col0], cb1 = s_cb[col0 + 1];
        int f0 = s_flag[r0 * 4 + head], f1 = s_flag[r1 * 4 + head];
        float t00 = ssp(C[nt][0] + cb0 + (f0 ? vb0 : 0.f));
        float t01 = ssp(C[nt][1] + cb1 + (f0 ? vb1 : 0.f));
        float t10 = ssp(C[nt][2] + cb0 + (f1 ? vb0 : 0.f));
        float t11 = ssp(C[nt][3] + cb1 + (f1 ? vb1 : 0.f));
        in32[r0 * 68 + col0 / 2] = h2(t00, t01);
        in32[r1 * 68 + col0 / 2] = h2(t10, t11);
    }
    __syncthreads();

    float D[4][4];
#pragma unroll
    for (int nt = 0; nt < 4; nt++)
        D[nt][0] = D[nt][1] = D[nt][2] = D[nt][3] = 0.f;
#pragma unroll
    for (int kk = 0; kk < 4; kk++) {
        u32 A[4];
        A[0] = in32[r0 * 68 + kk * 8 + t];
        A[1] = in32[r1 * 68 + kk * 8 + t];
        A[2] = in32[r0 * 68 + kk * 8 + 4 + t];
        A[3] = in32[r1 * 68 + kk * 8 + 4 + t];
#pragma unroll
        for (int nt = 0; nt < 4; nt++) {
            int j = (nh * 4 + nt) * 8 + g;
            u32 B[2];
            B[0] = s_w2[j * 33 + kk * 8 + t];
            B[1] = s_w2[j * 33 + kk * 8 + 4 + t];
            mma16816(D[nt], A, B);
        }
    }

    int nn0 = n0 + r0, nn1 = n0 + r1;
#pragma unroll
    for (int nt = 0; nt < 4; nt++) {
        int col = (nh * 4 + nt) * 8 + 2 * t;
        float ob0 = s_ob[col], ob1 = s_ob[col + 1];
        if (nn0 < NN)
            *reinterpret_cast<float2*>(y + (size_t)nn0 * HCH + col) =
                make_float2(D[nt][0] + ob0, D[nt][1] + ob1);
        if (nn1 < NN)
            *reinterpret_cast<float2*>(y + (size_t)nn1 * HCH + col) =
                make_float2(D[nt][2] + ob0, D[nt][3] + ob1);
    }
}

// ---------------------------------------------------------------------------
extern "C" void kernel_launch(void* const* d_in, const int* in_sizes, int n_in,
                              void* d_out, int out_size) {
    const float* x    = (const float*)d_in[0];
    const int*   ei   = (const int*)d_in[1];
    const float* ea   = (const float*)d_in[2];
    const float* kw   = (const float*)d_in[3];
    const float* qw   = (const float*)d_in[4];
    const float* vw   = (const float*)d_in[5];
    const float* wk1  = (const float*)d_in[6];
    const float* bk1  = (const float*)d_in[7];
    const float* wk2  = (const float*)d_in[8];
    const float* bk2  = (const float*)d_in[9];
    const float* wklw = (const float*)d_in[10];
    const float* wklb = (const float*)d_in[11];
    const float* wv1  = (const float*)d_in[12];
    const float* bv1  = (const float*)d_in[13];
    const float* wv2  = (const float*)d_in[14];
    const float* bv2  = (const float*)d_in[15];
    const float* wvlw = (const float*)d_in[16];
    const float* wvlb = (const float*)d_in[17];
    const float* cenw = (const float*)d_in[18];
    const float* cenb = (const float*)d_in[19];
    const float* outw = (const float*)d_in[20];
    const float* outb = (const float*)d_in[21];
    float* out = (float*)d_out;

    // 4 launches; k_out is launch index 3 -> profiled by ncu next round.
    k_nodes<<<(NN * NHD + 255) / 256, 256>>>(x, kw, qw, vw, wklw, wklb, ei);
    k_mlp<<<MLP_GRID, 256>>>(ea, wk1, bk1, wk2, bk2, wv1, bv1, wv2, bv2);
    k_attn<<<(EE * NHD) / 256, 256>>>(ei);
    k_out<<<(NN + 63) / 64, 256>>>(x, wvlw, wvlb, cenw, cenb,
                                   outw, outb, out);
}